// round 1
// baseline (speedup 1.0000x reference)
#include <cuda_runtime.h>

// ---------------------------------------------------------------------------
// 2-layer LSTM (H=64, T=15, latent=16), B=65536, out [B,15,1] fp32.
// Round 0 baseline: fp32 SIMT thread-per-row with packed f32x2 FMAs.
//   K0: layer-0 recurrence, h in SMEM (private per-thread columns), c in regs,
//       gate-interleaved weights in SMEM (LDS.128 broadcast). Writes h1 to a
//       __device__ buffer laid out [t][k][row] (coalesced both ways).
//   K1: layer-1 recurrence + fc epilogue, h1 via coalesced LDG (L2-resident).
// ---------------------------------------------------------------------------

#define ULL unsigned long long

constexpr int BATCH = 65536;
constexpr int T     = 15;

// inter-layer activations: [t][k][row] fp32 = 15*64*65536*4 = 252MB
__device__ float g_h1[(size_t)T * 64 * BATCH];

// ---- packed fp32x2 helpers (sm_100+) --------------------------------------
__device__ __forceinline__ ULL pk2(float x) {
    ULL r;
    asm("mov.b64 %0, {%1, %2};" : "=l"(r) : "f"(x), "f"(x));
    return r;
}
__device__ __forceinline__ void fma2(ULL& d, ULL a, ULL b) {
    asm("fma.rn.f32x2 %0, %1, %2, %0;" : "+l"(d) : "l"(a), "l"(b));
}
__device__ __forceinline__ float2 upk(ULL v) {
    float lo, hi;
    asm("mov.b64 {%0, %1}, %2;" : "=f"(lo), "=f"(hi) : "l"(v));
    return make_float2(lo, hi);
}

// ---- accurate-enough activations (EX2-based, ~2^-22 rel err) --------------
__device__ __forceinline__ float sigf(float x) {
    return __fdividef(1.0f, 1.0f + __expf(-x));
}
__device__ __forceinline__ float tanh_(float x) {
    float e = __expf(-2.0f * fabsf(x));
    float r = __fdividef(1.0f - e, 1.0f + e);
    return copysignf(r, x);
}

// ===========================================================================
// K0: layer 0.  gates = z@Wih0^T + h@Whh0^T + (bih0+bhh0); z part is folded
// into every step (z is time-constant input).
// ===========================================================================
constexpr int NT0 = 256;
// SMEM float offsets:
//   sWh [k<64][j<64][g<4] : 0      .. 16384
//   sWz [k<16][j][g]      : 16384  .. 20480
//   sB  [j][g]            : 20480  .. 20736
//   sH  [k<64][tid]       : 20736  .. 37120
//   sZ  (ULL) [k<16][tid] : byte offset 148480, 16*256*8 = 32768 bytes
constexpr int SM0_BYTES = 37120 * 4 + 16 * NT0 * 8;   // 181248 B

__global__ void __launch_bounds__(NT0, 1) lstm0_kernel(
    const float* __restrict__ z,   const float* __restrict__ Wih,
    const float* __restrict__ Whh, const float* __restrict__ bih,
    const float* __restrict__ bhh)
{
    extern __shared__ float sm[];
    float* sWh = sm;
    float* sWz = sm + 16384;
    float* sB  = sm + 20480;
    float* sH  = sm + 20736;
    ULL*   sZ  = (ULL*)(sm + 37120);
    const int tid = threadIdx.x;

    // weight repack: gate-interleaved [k][j][4]
    for (int idx = tid; idx < 64 * 256; idx += NT0) {
        int k = idx >> 8, j = (idx >> 2) & 63, g = idx & 3;
        sWh[idx] = Whh[(g * 64 + j) * 64 + k];
    }
    for (int idx = tid; idx < 16 * 256; idx += NT0) {
        int k = idx >> 8, j = (idx >> 2) & 63, g = idx & 3;
        sWz[idx] = Wih[(g * 64 + j) * 16 + k];
    }
    for (int idx = tid; idx < 256; idx += NT0) {
        int j = idx >> 2, g = idx & 3;
        sB[idx] = bih[g * 64 + j] + bhh[g * 64 + j];
    }
    __syncthreads();

    const int row = blockIdx.x * NT0 + tid;

    #pragma unroll
    for (int k = 0; k < 16; k++)
        sZ[k * NT0 + tid] = pk2(z[row * 16 + k]);

    float c[64], hn[64];
    #pragma unroll
    for (int j = 0; j < 64; j++) { c[j] = 0.0f; sH[j * NT0 + tid] = 0.0f; }

    for (int t = 0; t < T; t++) {
        float* h1out = g_h1 + (size_t)t * 64 * BATCH + row;
        #pragma unroll
        for (int jt = 0; jt < 8; jt++) {
            ULL a0[8], a1[8];                       // (i,f) and (g,o) pairs
            #pragma unroll
            for (int jj = 0; jj < 8; jj++) {
                ulonglong2 bv = *(const ulonglong2*)(sB + (jt * 8 + jj) * 4);
                a0[jj] = bv.x; a1[jj] = bv.y;
            }
            // z contribution (K=16)
            #pragma unroll 2
            for (int k = 0; k < 16; k++) {
                ULL zp = sZ[k * NT0 + tid];
                const float* wrow = sWz + k * 256 + jt * 32;
                #pragma unroll
                for (int jj = 0; jj < 8; jj++) {
                    ulonglong2 w = *(const ulonglong2*)(wrow + jj * 4);
                    fma2(a0[jj], zp, w.x);
                    fma2(a1[jj], zp, w.y);
                }
            }
            // recurrent contribution (K=64); h == 0 at t == 0
            if (t > 0) {
                #pragma unroll 2
                for (int k = 0; k < 64; k++) {
                    ULL hp = pk2(sH[k * NT0 + tid]);
                    const float* wrow = sWh + k * 256 + jt * 32;
                    #pragma unroll
                    for (int jj = 0; jj < 8; jj++) {
                        ulonglong2 w = *(const ulonglong2*)(wrow + jj * 4);
                        fma2(a0[jj], hp, w.x);
                        fma2(a1[jj], hp, w.y);
                    }
                }
            }
            #pragma unroll
            for (int jj = 0; jj < 8; jj++) {
                const int j = jt * 8 + jj;
                float2 v0 = upk(a0[jj]);   // i, f
                float2 v1 = upk(a1[jj]);   // g, o
                float ig = sigf(v0.x), fg = sigf(v0.y);
                float gg = tanh_(v1.x), og = sigf(v1.y);
                float cn = fg * c[j] + ig * gg;
                c[j]  = cn;
                hn[j] = og * tanh_(cn);
            }
        }
        #pragma unroll
        for (int j = 0; j < 64; j++) {
            sH[j * NT0 + tid] = hn[j];       // next-step state
            h1out[(size_t)j * BATCH] = hn[j]; // coalesced across warp
        }
    }
}

// ===========================================================================
// K1: layer 1 + fc.  gates = h1[t]@Wih1^T + h2@Whh1^T + (bih1+bhh1);
// out[b,t] = h2 . wfc + bfc
// ===========================================================================
constexpr int NT1 = 256;
// SMEM float offsets: sWi 0..16384, sWh 16384..32768, sB 32768..33024,
//                     sF 33024..33088, sH 33088..49472
constexpr int SM1_BYTES = 49472 * 4;   // 197888 B

__global__ void __launch_bounds__(NT1, 1) lstm1_kernel(
    const float* __restrict__ Wih, const float* __restrict__ Whh,
    const float* __restrict__ bih, const float* __restrict__ bhh,
    const float* __restrict__ Wfc, const float* __restrict__ bfc,
    float* __restrict__ out)
{
    extern __shared__ float sm[];
    float* sWi = sm;
    float* sWh = sm + 16384;
    float* sB  = sm + 32768;
    float* sF  = sm + 33024;
    float* sH  = sm + 33088;
    const int tid = threadIdx.x;

    for (int idx = tid; idx < 64 * 256; idx += NT1) {
        int k = idx >> 8, j = (idx >> 2) & 63, g = idx & 3;
        sWi[idx] = Wih[(g * 64 + j) * 64 + k];
        sWh[idx] = Whh[(g * 64 + j) * 64 + k];
    }
    for (int idx = tid; idx < 256; idx += NT1) {
        int j = idx >> 2, g = idx & 3;
        sB[idx] = bih[g * 64 + j] + bhh[g * 64 + j];
    }
    if (tid < 64) sF[tid] = Wfc[tid];
    __syncthreads();

    const int row = blockIdx.x * NT1 + tid;
    const float bf = __ldg(bfc);

    float c[64], hn[64];
    #pragma unroll
    for (int j = 0; j < 64; j++) { c[j] = 0.0f; sH[j * NT1 + tid] = 0.0f; }

    for (int t = 0; t < T; t++) {
        const float* h1p = g_h1 + (size_t)t * 64 * BATCH + row;
        float fcacc = 0.0f;
        #pragma unroll
        for (int jt = 0; jt < 8; jt++) {
            ULL a0[8], a1[8];
            #pragma unroll
            for (int jj = 0; jj < 8; jj++) {
                ulonglong2 bv = *(const ulonglong2*)(sB + (jt * 8 + jj) * 4);
                a0[jj] = bv.x; a1[jj] = bv.y;
            }
            // input contribution from h1[t] (K=64), direct LDG (L2-resident)
            for (int kg = 0; kg < 8; kg++) {
                float v[8];
                #pragma unroll
                for (int q = 0; q < 8; q++)
                    v[q] = h1p[(size_t)(kg * 8 + q) * BATCH];
                const float* wbase = sWi + kg * 8 * 256 + jt * 32;
                #pragma unroll
                for (int q = 0; q < 8; q++) {
                    ULL hp = pk2(v[q]);
                    #pragma unroll
                    for (int jj = 0; jj < 8; jj++) {
                        ulonglong2 w = *(const ulonglong2*)(wbase + q * 256 + jj * 4);
                        fma2(a0[jj], hp, w.x);
                        fma2(a1[jj], hp, w.y);
                    }
                }
            }
            // recurrent contribution (K=64); h2 == 0 at t == 0
            if (t > 0) {
                #pragma unroll 2
                for (int k = 0; k < 64; k++) {
                    ULL hp = pk2(sH[k * NT1 + tid]);
                    const float* wrow = sWh + k * 256 + jt * 32;
                    #pragma unroll
                    for (int jj = 0; jj < 8; jj++) {
                        ulonglong2 w = *(const ulonglong2*)(wrow + jj * 4);
                        fma2(a0[jj], hp, w.x);
                        fma2(a1[jj], hp, w.y);
                    }
                }
            }
            #pragma unroll
            for (int jj = 0; jj < 8; jj++) {
                const int j = jt * 8 + jj;
                float2 v0 = upk(a0[jj]);   // i, f
                float2 v1 = upk(a1[jj]);   // g, o
                float ig = sigf(v0.x), fg = sigf(v0.y);
                float gg = tanh_(v1.x), og = sigf(v1.y);
                float cn = fg * c[j] + ig * gg;
                c[j]  = cn;
                float h = og * tanh_(cn);
                hn[j] = h;
                fcacc += h * sF[j];
            }
        }
        #pragma unroll
        for (int j = 0; j < 64; j++) sH[j * NT1 + tid] = hn[j];
        out[row * T + t] = fcacc + bf;
    }
}

// ===========================================================================
extern "C" void kernel_launch(void* const* d_in, const int* in_sizes, int n_in,
                              void* d_out, int out_size)
{
    const float* z    = (const float*)d_in[0];
    const float* Wih0 = (const float*)d_in[1];
    const float* Whh0 = (const float*)d_in[2];
    const float* bih0 = (const float*)d_in[3];
    const float* bhh0 = (const float*)d_in[4];
    const float* Wih1 = (const float*)d_in[5];
    const float* Whh1 = (const float*)d_in[6];
    const float* bih1 = (const float*)d_in[7];
    const float* bhh1 = (const float*)d_in[8];
    const float* Wfc  = (const float*)d_in[9];
    const float* bfc  = (const float*)d_in[10];
    float* out = (float*)d_out;

    const int B = in_sizes[0] / 16;   // 65536

    cudaFuncSetAttribute(lstm0_kernel, cudaFuncAttributeMaxDynamicSharedMemorySize, SM0_BYTES);
    cudaFuncSetAttribute(lstm1_kernel, cudaFuncAttributeMaxDynamicSharedMemorySize, SM1_BYTES);

    lstm0_kernel<<<B / NT0, NT0, SM0_BYTES>>>(z, Wih0, Whh0, bih0, bhh0);
    lstm1_kernel<<<B / NT1, NT1, SM1_BYTES>>>(Wih1, Whh1, bih1, bhh1, Wfc, bfc, out);
}

// round 5
// speedup vs baseline: 4.6345x; 4.6345x over previous
#include <cuda_runtime.h>
#include <cuda_bf16.h>
#include <cstdint>

#define DI __device__ __forceinline__

constexpr int T  = 15;
constexpr int NT = 256;      // 8 warps
constexpr int MR = 64;       // batch rows per CTA

// ---------------- SMEM byte offsets ----------------
// Weight tiles: [256 n'][64 k] bf16, 128B rows, SW128 xor swizzle (32768 B each)
constexpr int O_W0HH = 0;         // Whh0 hi
constexpr int O_W0HL = 32768;     // Whh0 lo
constexpr int O_W1IH = 65536;     // Wih1 hi
constexpr int O_W1IL = 98304;     // Wih1 lo
constexpr int O_W1HH = 131072;    // Whh1 hi
constexpr int O_W1HL = 163840;    // Whh1 lo
// h-state tiles: [64 rows][64 k] bf16 SW128 (8192 B each)
constexpr int O_H0H  = 196608;
constexpr int O_H0L  = 204800;
constexpr int O_H1H  = 212992;
constexpr int O_H1L  = 221184;
constexpr int O_BIAS1 = 229376;   // 64 x float4 (i,f,g,o)
constexpr int O_FCW   = 230400;   // 64 floats
constexpr int O_SRED  = 230656;   // 64 x 2 floats
constexpr int SMEM_TOTAL = 231168;

DI uint32_t smem_u32(const void* p) {
    uint32_t a;
    asm("{ .reg .u64 t; cvta.to.shared.u64 t, %1; cvt.u32.u64 %0, t; }" : "=r"(a) : "l"(p));
    return a;
}
DI void sts16(uint32_t addr, __nv_bfloat16 v) {
    unsigned short u = *reinterpret_cast<unsigned short*>(&v);
    asm volatile("st.shared.b16 [%0], %1;" :: "r"(addr), "h"(u) : "memory");
}
DI void ldsm4(uint32_t* r, uint32_t addr) {
    asm volatile("ldmatrix.sync.aligned.m8n8.x4.shared.b16 {%0,%1,%2,%3}, [%4];"
                 : "=r"(r[0]), "=r"(r[1]), "=r"(r[2]), "=r"(r[3]) : "r"(addr));
}
DI void mma4(float* d, const uint32_t* a, uint32_t b0, uint32_t b1, const float* c) {
    asm("mma.sync.aligned.m16n8k16.row.col.f32.bf16.bf16.f32 "
        "{%0,%1,%2,%3},{%4,%5,%6,%7},{%8,%9},{%10,%11,%12,%13};"
        : "=f"(d[0]), "=f"(d[1]), "=f"(d[2]), "=f"(d[3])
        : "r"(a[0]), "r"(a[1]), "r"(a[2]), "r"(a[3]), "r"(b0), "r"(b1),
          "f"(c[0]), "f"(c[1]), "f"(c[2]), "f"(c[3]));
}

// swizzled offset inside a [n'][64k] bf16 tile with 128B rows
DI uint32_t swoff(int np, int k) {
    return (uint32_t)(np * 128 + k * 2) ^ (uint32_t)((np & 7) << 4);
}

// ---- exact activations (EX2 + RCP, rel err ~2^-22) ----
DI float sigf(float x)  { return __fdividef(1.0f, 1.0f + __expf(-x)); }
DI float tanh_(float x) {
    float e = __expf(-2.0f * fabsf(x));
    return copysignf(__fdividef(1.0f - e, 1.0f + e), x);
}

// 3-term split-bf16 GEMM, accumulate into D[64]:
// D += Ahi*Bhi + Alo*Bhi + Ahi*Blo over K=64, warp n-range 128 (8 chunks of 16)
DI void gemm3acc(float* D, uint32_t aHi, uint32_t aLo, uint32_t bHi, uint32_t bLo,
                 uint32_t akl, uint32_t axm, uint32_t bkl, uint32_t bxm)
{
    #pragma unroll
    for (int ks = 0; ks < 4; ks++) {
        const uint32_t kA = ((uint32_t)(ks * 32) + akl) ^ axm;
        const uint32_t kB = ((uint32_t)(ks * 32) + bkl) ^ bxm;
        uint32_t ah[4], al[4];
        ldsm4(ah, aHi + kA);
        ldsm4(al, aLo + kA);
        #pragma unroll
        for (int p = 0; p < 8; p++) {
            uint32_t bh[4], bl[4];
            ldsm4(bh, bHi + p * 2048 + kB);
            ldsm4(bl, bLo + p * 2048 + kB);
            float* d0 = D + p * 8;
            mma4(d0,     ah, bh[0], bh[1], d0);
            mma4(d0 + 4, ah, bh[2], bh[3], d0 + 4);
            mma4(d0,     al, bh[0], bh[1], d0);
            mma4(d0 + 4, al, bh[2], bh[3], d0 + 4);
            mma4(d0,     ah, bl[0], bl[1], d0);
            mma4(d0 + 4, ah, bl[2], bl[3], d0 + 4);
        }
    }
}

// epilogue: gate exchange, LSTM cell update, h split writeback. LAYER 1 adds
// bias (layer-0 bias is folded into zp) and accumulates the fc dot product.
template<int LAYER>
DI float epilogue(float* D, float* cs, int odd, int jconst,
                  uint32_t eHi, uint32_t eLo, uint32_t exm,
                  const float4* sBias1, const float* sFcw)
{
    float fcacc = 0.0f;
    #pragma unroll
    for (int p = 0; p < 8; p++) {
        #pragma unroll
        for (int q = 0; q < 2; q++) {
            const int di = p * 8 + q * 4;
            float x0 = D[di], x1 = D[di + 1], x2 = D[di + 2], x3 = D[di + 3];
            float e1 = __shfl_xor_sync(0xffffffffu, odd ? x0 : x2, 1);
            float e2 = __shfl_xor_sync(0xffffffffu, odd ? x1 : x3, 1);
            float gi = odd ? e1 : x0;
            float gf = odd ? e2 : x1;
            float gg = odd ? x2 : e1;
            float go = odd ? x3 : e2;
            const int j = jconst + p * 4 + q * 2;
            if (LAYER == 1) {
                const float4 b = sBias1[j];
                gi += b.x; gf += b.y; gg += b.z; go += b.w;
            }
            const float i_ = sigf(gi);
            const float f_ = sigf(gf);
            const float g_ = tanh_(gg);
            const float o_ = sigf(go);
            const int ci = p * 2 + q;
            const float cn = fmaf(f_, cs[ci], i_ * g_);
            cs[ci] = cn;
            const float h = o_ * tanh_(cn);
            if (LAYER == 1) fcacc = fmaf(h, sFcw[j], fcacc);
            const __nv_bfloat16 hh = __float2bfloat16(h);
            const float lo = h - __bfloat162float(hh);
            const uint32_t co = ((uint32_t)(j * 2)) ^ exm;
            sts16(eHi + co, hh);
            sts16(eLo + co, __float2bfloat16(lo));
        }
    }
    return fcacc;
}

// ===========================================================================
__global__ void __launch_bounds__(NT, 1) lstm_hmma_kernel(
    const float* __restrict__ z,
    const float* __restrict__ Wih0, const float* __restrict__ Whh0,
    const float* __restrict__ bih0, const float* __restrict__ bhh0,
    const float* __restrict__ Wih1, const float* __restrict__ Whh1,
    const float* __restrict__ bih1, const float* __restrict__ bhh1,
    const float* __restrict__ Wfc,  const float* __restrict__ bfc,
    float* __restrict__ out)
{
    extern __shared__ char sm[];
    const uint32_t smb = smem_u32(sm);
    const int tid  = threadIdx.x;
    const int lane = tid & 31;
    const int w    = tid >> 5;
    const int mg   = w >> 1;       // row group: rows mg*16 .. +15
    const int ng   = w & 1;        // n-half: n' in [ng*128, ng*128+128)

    // ---- ldmatrix lane addressing constants ----
    const int j8  = lane & 7;
    const int sel = lane >> 3;
    const int arow = mg * 16 + j8 + (sel & 1) * 8;      // local A row this lane feeds
    const uint32_t axm = (uint32_t)j8 << 4;             // arow & 7 == j8
    const uint32_t akl = (uint32_t)(sel >> 1) << 4;
    const int bnl = (sel >> 1) * 8 + j8;                // B row within 16-row chunk
    const uint32_t bxm = (uint32_t)j8 << 4;
    const uint32_t bkl = (uint32_t)(sel & 1) << 4;

    const uint32_t aOff = (uint32_t)arow * 128;
    const uint32_t bOff = (uint32_t)(ng * 128 + bnl) * 128;
    const uint32_t aH0H = smb + O_H0H + aOff, aH0L = smb + O_H0L + aOff;
    const uint32_t aH1H = smb + O_H1H + aOff, aH1L = smb + O_H1L + aOff;
    const uint32_t bW0H = smb + O_W0HH + bOff, bW0L = smb + O_W0HL + bOff;
    const uint32_t bW1IH = smb + O_W1IH + bOff, bW1IL = smb + O_W1IL + bOff;
    const uint32_t bW1HH = smb + O_W1HH + bOff, bW1HL = smb + O_W1HL + bOff;

    // ---- epilogue lane constants ----
    const int gid = lane >> 2, tig = lane & 3;
    const int odd = tig & 1;
    const int erow = mg * 16 + gid + 8 * odd;           // local row this lane updates
    const uint32_t eOff = (uint32_t)erow * 128;
    const uint32_t exm  = (uint32_t)(erow & 7) << 4;
    const uint32_t eH0H = smb + O_H0H + eOff, eH0L = smb + O_H0L + eOff;
    const uint32_t eH1H = smb + O_H1H + eOff, eH1L = smb + O_H1L + eOff;
    const int jconst = ng * 32 + (tig >> 1);

    float4* sBias1 = (float4*)(sm + O_BIAS1);
    float*  sFcw   = (float*)(sm + O_FCW);
    float*  sRed   = (float*)(sm + O_SRED);

    // ======== init: repack weights (split bf16, gate-interleaved n'=4j+g) ========
    for (int idx = tid; idx < 16384; idx += NT) {
        const int r = idx >> 6, k = idx & 63;
        const int g = r >> 6, j = r & 63;
        const uint32_t off = swoff(j * 4 + g, k);
        float v; __nv_bfloat16 h;
        v = Whh0[idx]; h = __float2bfloat16(v);
        *(__nv_bfloat16*)(sm + O_W0HH + off) = h;
        *(__nv_bfloat16*)(sm + O_W0HL + off) = __float2bfloat16(v - __bfloat162float(h));
        v = Wih1[idx]; h = __float2bfloat16(v);
        *(__nv_bfloat16*)(sm + O_W1IH + off) = h;
        *(__nv_bfloat16*)(sm + O_W1IL + off) = __float2bfloat16(v - __bfloat162float(h));
        v = Whh1[idx]; h = __float2bfloat16(v);
        *(__nv_bfloat16*)(sm + O_W1HH + off) = h;
        *(__nv_bfloat16*)(sm + O_W1HL + off) = __float2bfloat16(v - __bfloat162float(h));
    }
    // stage Wih0 (fp32) into the h-tile area (16KB) + bias0 sums (1KB)
    float* sWz = (float*)(sm + O_H0H);     // [256][16] fp32
    float* sB0 = (float*)(sm + O_H1H);     // [256]
    for (int idx = tid; idx < 4096; idx += NT) sWz[idx] = Wih0[idx];
    for (int idx = tid; idx < 256;  idx += NT) sB0[idx] = bih0[idx] + bhh0[idx];
    if (tid < 64) {
        sBias1[tid] = make_float4(bih1[tid] + bhh1[tid],
                                  bih1[64 + tid] + bhh1[64 + tid],
                                  bih1[128 + tid] + bhh1[128 + tid],
                                  bih1[192 + tid] + bhh1[192 + tid]);
        sFcw[tid] = Wfc[tid];
    }
    const float bfc_v = __ldg(bfc);
    __syncthreads();

    // ======== one-time exact z-projection + bias0 into zp (D-fragment layout) ====
    const int gbase = blockIdx.x * MR;
    float zp[64];
    {
        float zr0[16], zr1[16];
        const int r0 = gbase + mg * 16 + gid;
        #pragma unroll
        for (int k = 0; k < 16; k++) {
            zr0[k] = z[(size_t)r0 * 16 + k];
            zr1[k] = z[(size_t)(r0 + 8) * 16 + k];
        }
        #pragma unroll
        for (int p = 0; p < 8; p++) {
            #pragma unroll
            for (int q = 0; q < 2; q++) {
                #pragma unroll
                for (int e = 0; e < 2; e++) {
                    const int np = ng * 128 + p * 16 + q * 8 + tig * 2 + e;
                    const int orig = (np & 3) * 64 + (np >> 2);
                    const float* wr = sWz + orig * 16;
                    float s0 = sB0[orig], s1 = s0;
                    #pragma unroll
                    for (int k = 0; k < 16; k++) {
                        const float wv = wr[k];
                        s0 = fmaf(zr0[k], wv, s0);
                        s1 = fmaf(zr1[k], wv, s1);
                    }
                    zp[p * 8 + q * 4 + e]     = s0;
                    zp[p * 8 + q * 4 + 2 + e] = s1;
                }
            }
        }
    }
    __syncthreads();   // staging reads done before h tiles get overwritten

    // ======== recurrence ========
    float cs0[16], cs1[16];
    #pragma unroll
    for (int i = 0; i < 16; i++) { cs0[i] = 0.0f; cs1[i] = 0.0f; }

    #pragma unroll 1
    for (int t = 0; t < T; t++) {
        float D[64];

        // ----- layer 0: D = zp (+ h0(t-1)·Whh0, 3-term) -----
        #pragma unroll
        for (int i = 0; i < 64; i++) D[i] = zp[i];
        if (t > 0) gemm3acc(D, aH0H, aH0L, bW0H, bW0L, akl, axm, bkl, bxm);
        __syncthreads();                                   // h0 reads done
        epilogue<0>(D, cs0, odd, jconst, eH0H, eH0L, exm, sBias1, sFcw);
        __syncthreads();                                   // h0(t) visible

        // ----- layer 1: D = h0(t)·Wih1 (+ h1(t-1)·Whh1) -----
        #pragma unroll
        for (int i = 0; i < 64; i++) D[i] = 0.0f;
        gemm3acc(D, aH0H, aH0L, bW1IH, bW1IL, akl, axm, bkl, bxm);
        if (t > 0) gemm3acc(D, aH1H, aH1L, bW1HH, bW1HL, akl, axm, bkl, bxm);
        __syncthreads();                                   // h1 reads done
        float fcacc = epilogue<1>(D, cs1, odd, jconst, eH1H, eH1L, exm, sBias1, sFcw);

        // fc reduction: combine the two lanes sharing a row, stash per (row, ng)
        fcacc += __shfl_xor_sync(0xffffffffu, fcacc, 2);
        if (tig == 0)      sRed[(mg * 16 + gid) * 2 + ng]     = fcacc;
        else if (tig == 1) sRed[(mg * 16 + gid + 8) * 2 + ng] = fcacc;
        __syncthreads();                                   // h1(t) + sRed visible
        if (tid < MR)
            out[(size_t)(gbase + tid) * T + t] = sRed[2 * tid] + sRed[2 * tid + 1] + bfc_v;
    }
}

// ===========================================================================
extern "C" void kernel_launch(void* const* d_in, const int* in_sizes, int n_in,
                              void* d_out, int out_size)
{
    const float* z    = (const float*)d_in[0];
    const float* Wih0 = (const float*)d_in[1];
    const float* Whh0 = (const float*)d_in[2];
    const float* bih0 = (const float*)d_in[3];
    const float* bhh0 = (const float*)d_in[4];
    const float* Wih1 = (const float*)d_in[5];
    const float* Whh1 = (const float*)d_in[6];
    const float* bih1 = (const float*)d_in[7];
    const float* bhh1 = (const float*)d_in[8];
    const float* Wfc  = (const float*)d_in[9];
    const float* bfc  = (const float*)d_in[10];
    float* out = (float*)d_out;

    const int B = in_sizes[0] / 16;      // 65536

    cudaFuncSetAttribute(lstm_hmma_kernel,
                         cudaFuncAttributeMaxDynamicSharedMemorySize, SMEM_TOTAL);
    lstm_hmma_kernel<<<B / MR, NT, SMEM_TOTAL>>>(
        z, Wih0, Whh0, bih0, bhh0, Wih1, Whh1, bih1, bhh1, Wfc, bfc, out);
}

// round 8
// speedup vs baseline: 6.0252x; 1.3001x over previous
#include <cuda_runtime.h>
#include <cuda_bf16.h>
#include <cstdint>

#define DI __device__ __forceinline__

constexpr int T  = 15;
constexpr int NT = 512;      // 16 warps: 4 groups x 4 warps
constexpr int MR = 64;       // batch rows per CTA (16 per group)

// ---------------- SMEM byte offsets ----------------
// Weight tiles: [256 n'][64 k] bf16, 128B rows, SW128 xor swizzle (32768 B each)
constexpr int O_W0HH = 0;         // Whh0 hi
constexpr int O_W0HL = 32768;     // Whh0 lo
constexpr int O_W1IH = 65536;     // Wih1 hi
constexpr int O_W1IL = 98304;     // Wih1 lo
constexpr int O_W1HH = 131072;    // Whh1 hi
constexpr int O_W1HL = 163840;    // Whh1 lo
// h-state tiles: [64 rows][64 k] bf16 SW128 (8192 B each)
constexpr int O_H0H  = 196608;
constexpr int O_H0L  = 204800;
constexpr int O_H1H  = 212992;
constexpr int O_H1L  = 221184;
constexpr int O_BIAS1 = 229376;   // 64 x float4 (i,f,g,o)
constexpr int O_FCW   = 230400;   // 64 floats
constexpr int O_SRED  = 230656;   // 64 rows x 4 floats
constexpr int SMEM_TOTAL = 231680;

DI uint32_t smem_u32(const void* p) {
    uint32_t a;
    asm("{ .reg .u64 t; cvta.to.shared.u64 t, %1; cvt.u32.u64 %0, t; }" : "=r"(a) : "l"(p));
    return a;
}
DI void sts16(uint32_t addr, __nv_bfloat16 v) {
    unsigned short u = *reinterpret_cast<unsigned short*>(&v);
    asm volatile("st.shared.b16 [%0], %1;" :: "r"(addr), "h"(u) : "memory");
}
DI void ldsm4(uint32_t* r, uint32_t addr) {
    asm volatile("ldmatrix.sync.aligned.m8n8.x4.shared.b16 {%0,%1,%2,%3}, [%4];"
                 : "=r"(r[0]), "=r"(r[1]), "=r"(r[2]), "=r"(r[3]) : "r"(addr));
}
DI void mma4(float* d, const uint32_t* a, uint32_t b0, uint32_t b1, const float* c) {
    asm("mma.sync.aligned.m16n8k16.row.col.f32.bf16.bf16.f32 "
        "{%0,%1,%2,%3},{%4,%5,%6,%7},{%8,%9},{%10,%11,%12,%13};"
        : "=f"(d[0]), "=f"(d[1]), "=f"(d[2]), "=f"(d[3])
        : "r"(a[0]), "r"(a[1]), "r"(a[2]), "r"(a[3]), "r"(b0), "r"(b1),
          "f"(c[0]), "f"(c[1]), "f"(c[2]), "f"(c[3]));
}
// named barrier: per-group sync (128 threads), with memory ordering
DI void bar_grp(int id) {
    asm volatile("bar.sync %0, 128;" :: "r"(id) : "memory");
}

// swizzled offset inside a [n'][64k] bf16 tile with 128B rows
DI uint32_t swoff(int np, int k) {
    return (uint32_t)(np * 128 + k * 2) ^ (uint32_t)((np & 7) << 4);
}

// ---- exact activations (EX2 + RCP, rel err ~2^-22) ----
DI float sigf(float x)  { return __fdividef(1.0f, 1.0f + __expf(-x)); }
DI float tanh_(float x) {
    float e = __expf(-2.0f * fabsf(x));
    return copysignf(__fdividef(1.0f - e, 1.0f + e), x);
}

// 3-term split-bf16 GEMM, accumulate into D[32]:
// D += Ahi*Bhi + Alo*Bhi + Ahi*Blo over K=64; warp n-range = 64 (4 chunks of 16)
DI void gemm3acc(float* D, uint32_t aHi, uint32_t aLo, uint32_t bHi, uint32_t bLo,
                 uint32_t akl, uint32_t axm, uint32_t bkl, uint32_t bxm)
{
    #pragma unroll
    for (int ks = 0; ks < 4; ks++) {
        const uint32_t kA = ((uint32_t)(ks * 32) + akl) ^ axm;
        const uint32_t kB = ((uint32_t)(ks * 32) + bkl) ^ bxm;
        uint32_t ah[4], al[4];
        ldsm4(ah, aHi + kA);
        ldsm4(al, aLo + kA);
        #pragma unroll
        for (int p = 0; p < 4; p++) {
            uint32_t bh[4], bl[4];
            ldsm4(bh, bHi + p * 2048 + kB);
            ldsm4(bl, bLo + p * 2048 + kB);
            float* d0 = D + p * 8;
            mma4(d0,     ah, bh[0], bh[1], d0);
            mma4(d0 + 4, ah, bh[2], bh[3], d0 + 4);
            mma4(d0,     al, bh[0], bh[1], d0);
            mma4(d0 + 4, al, bh[2], bh[3], d0 + 4);
            mma4(d0,     ah, bl[0], bl[1], d0);
            mma4(d0 + 4, ah, bl[2], bl[3], d0 + 4);
        }
    }
}

// epilogue: gate exchange, LSTM cell update, h split writeback. LAYER 1 adds
// bias (layer-0 bias folded into zp) and accumulates the fc dot product.
template<int LAYER>
DI float epilogue(float* D, float* cs, int odd, int jconst,
                  uint32_t eHi, uint32_t eLo, uint32_t exm,
                  const float4* sBias1, const float* sFcw)
{
    float fcacc = 0.0f;
    #pragma unroll
    for (int p = 0; p < 4; p++) {
        #pragma unroll
        for (int q = 0; q < 2; q++) {
            const int di = p * 8 + q * 4;
            float x0 = D[di], x1 = D[di + 1], x2 = D[di + 2], x3 = D[di + 3];
            float e1 = __shfl_xor_sync(0xffffffffu, odd ? x0 : x2, 1);
            float e2 = __shfl_xor_sync(0xffffffffu, odd ? x1 : x3, 1);
            float gi = odd ? e1 : x0;
            float gf = odd ? e2 : x1;
            float gg = odd ? x2 : e1;
            float go = odd ? x3 : e2;
            const int j = jconst + p * 4 + q * 2;
            if (LAYER == 1) {
                const float4 b = sBias1[j];
                gi += b.x; gf += b.y; gg += b.z; go += b.w;
            }
            const float i_ = sigf(gi);
            const float f_ = sigf(gf);
            const float g_ = tanh_(gg);
            const float o_ = sigf(go);
            const int ci = p * 2 + q;
            const float cn = fmaf(f_, cs[ci], i_ * g_);
            cs[ci] = cn;
            const float h = o_ * tanh_(cn);
            if (LAYER == 1) fcacc = fmaf(h, sFcw[j], fcacc);
            const __nv_bfloat16 hh = __float2bfloat16(h);
            const float lo = h - __bfloat162float(hh);
            const uint32_t co = ((uint32_t)(j * 2)) ^ exm;
            sts16(eHi + co, hh);
            sts16(eLo + co, __float2bfloat16(lo));
        }
    }
    return fcacc;
}

// ===========================================================================
__global__ void __launch_bounds__(NT, 1) lstm_hmma_kernel(
    const float* __restrict__ z,
    const float* __restrict__ Wih0, const float* __restrict__ Whh0,
    const float* __restrict__ bih0, const float* __restrict__ bhh0,
    const float* __restrict__ Wih1, const float* __restrict__ Whh1,
    const float* __restrict__ bih1, const float* __restrict__ bhh1,
    const float* __restrict__ Wfc,  const float* __restrict__ bfc,
    float* __restrict__ out)
{
    extern __shared__ char sm[];
    const uint32_t smb = smem_u32(sm);
    const int tid  = threadIdx.x;
    const int lane = tid & 31;
    const int w    = tid >> 5;
    const int grp  = w >> 2;       // row group: rows grp*16 .. +15
    const int ng   = w & 3;        // n-quarter: n' in [ng*64, ng*64+64)
    const int bid  = grp + 1;      // named barrier id

    // ---- ldmatrix lane addressing constants ----
    const int j8  = lane & 7;
    const int sel = lane >> 3;
    const int arow = grp * 16 + j8 + (sel & 1) * 8;     // local A row this lane feeds
    const uint32_t axm = (uint32_t)j8 << 4;             // arow & 7 == j8
    const uint32_t akl = (uint32_t)(sel >> 1) << 4;
    const int bnl = (sel >> 1) * 8 + j8;                // B row within 16-row chunk
    const uint32_t bxm = (uint32_t)j8 << 4;
    const uint32_t bkl = (uint32_t)(sel & 1) << 4;

    const uint32_t aOff = (uint32_t)arow * 128;
    const uint32_t bOff = (uint32_t)(ng * 64 + bnl) * 128;
    const uint32_t aH0H = smb + O_H0H + aOff, aH0L = smb + O_H0L + aOff;
    const uint32_t aH1H = smb + O_H1H + aOff, aH1L = smb + O_H1L + aOff;
    const uint32_t bW0H = smb + O_W0HH + bOff, bW0L = smb + O_W0HL + bOff;
    const uint32_t bW1IH = smb + O_W1IH + bOff, bW1IL = smb + O_W1IL + bOff;
    const uint32_t bW1HH = smb + O_W1HH + bOff, bW1HL = smb + O_W1HL + bOff;

    // ---- epilogue lane constants ----
    const int gid = lane >> 2, tig = lane & 3;
    const int odd = tig & 1;
    const int erow = grp * 16 + gid + 8 * odd;          // local row this lane updates
    const uint32_t eOff = (uint32_t)erow * 128;
    const uint32_t exm  = (uint32_t)(erow & 7) << 4;
    const uint32_t eH0H = smb + O_H0H + eOff, eH0L = smb + O_H0L + eOff;
    const uint32_t eH1H = smb + O_H1H + eOff, eH1L = smb + O_H1L + eOff;
    const int jconst = ng * 16 + (tig >> 1);

    float4* sBias1 = (float4*)(sm + O_BIAS1);
    float*  sFcw   = (float*)(sm + O_FCW);
    float*  sRed   = (float*)(sm + O_SRED);

    // ======== init: repack weights (split bf16, gate-interleaved n'=4j+g) ========
    for (int idx = tid; idx < 16384; idx += NT) {
        const int r = idx >> 6, k = idx & 63;
        const int g = r >> 6, j = r & 63;
        const uint32_t off = swoff(j * 4 + g, k);
        float v; __nv_bfloat16 h;
        v = Whh0[idx]; h = __float2bfloat16(v);
        *(__nv_bfloat16*)(sm + O_W0HH + off) = h;
        *(__nv_bfloat16*)(sm + O_W0HL + off) = __float2bfloat16(v - __bfloat162float(h));
        v = Wih1[idx]; h = __float2bfloat16(v);
        *(__nv_bfloat16*)(sm + O_W1IH + off) = h;
        *(__nv_bfloat16*)(sm + O_W1IL + off) = __float2bfloat16(v - __bfloat162float(h));
        v = Whh1[idx]; h = __float2bfloat16(v);
        *(__nv_bfloat16*)(sm + O_W1HH + off) = h;
        *(__nv_bfloat16*)(sm + O_W1HL + off) = __float2bfloat16(v - __bfloat162float(h));
    }
    // stage Wih0 (fp32) into the h-tile area (16KB) + bias0 sums (1KB)
    float* sWz = (float*)(sm + O_H0H);     // [256][16] fp32
    float* sB0 = (float*)(sm + O_H1H);     // [256]
    for (int idx = tid; idx < 4096; idx += NT) sWz[idx] = Wih0[idx];
    for (int idx = tid; idx < 256;  idx += NT) sB0[idx] = bih0[idx] + bhh0[idx];
    if (tid < 64) {
        sBias1[tid] = make_float4(bih1[tid] + bhh1[tid],
                                  bih1[64 + tid] + bhh1[64 + tid],
                                  bih1[128 + tid] + bhh1[128 + tid],
                                  bih1[192 + tid] + bhh1[192 + tid]);
        sFcw[tid] = Wfc[tid];
    }
    const float bfc_v = __ldg(bfc);
    __syncthreads();

    // ======== one-time exact z-projection + bias0 into zp (D-fragment layout) ====
    const int gbase = blockIdx.x * MR;
    float zp[32];
    {
        float zr0[16], zr1[16];
        const int r0 = gbase + grp * 16 + gid;
        #pragma unroll
        for (int k = 0; k < 16; k++) {
            zr0[k] = z[(size_t)r0 * 16 + k];
            zr1[k] = z[(size_t)(r0 + 8) * 16 + k];
        }
        #pragma unroll
        for (int p = 0; p < 4; p++) {
            #pragma unroll
            for (int q = 0; q < 2; q++) {
                #pragma unroll
                for (int e = 0; e < 2; e++) {
                    const int np = ng * 64 + p * 16 + q * 8 + tig * 2 + e;
                    const int orig = (np & 3) * 64 + (np >> 2);
                    const float* wr = sWz + orig * 16;
                    float s0 = sB0[orig], s1 = s0;
                    #pragma unroll
                    for (int k = 0; k < 16; k++) {
                        const float wv = wr[k];
                        s0 = fmaf(zr0[k], wv, s0);
                        s1 = fmaf(zr1[k], wv, s1);
                    }
                    zp[p * 8 + q * 4 + e]     = s0;
                    zp[p * 8 + q * 4 + 2 + e] = s1;
                }
            }
        }
    }
    __syncthreads();   // staging reads done before h tiles get overwritten

    // ======== recurrence (each 16-row group runs independently) ========
    float cs0[8], cs1[8];
    #pragma unroll
    for (int i = 0; i < 8; i++) { cs0[i] = 0.0f; cs1[i] = 0.0f; }

    #pragma unroll 1
    for (int t = 0; t < T; t++) {
        float D[32];

        // ----- layer 0: D = zp (+ h0(t-1)·Whh0, 3-term) -----
        #pragma unroll
        for (int i = 0; i < 32; i++) D[i] = zp[i];
        if (t > 0) gemm3acc(D, aH0H, aH0L, bW0H, bW0L, akl, axm, bkl, bxm);
        bar_grp(bid);                                      // h0 reads done
        epilogue<0>(D, cs0, odd, jconst, eH0H, eH0L, exm, sBias1, sFcw);
        bar_grp(bid);                                      // h0(t) visible

        // ----- layer 1: D = h0(t)·Wih1 (+ h1(t-1)·Whh1) -----
        #pragma unroll
        for (int i = 0; i < 32; i++) D[i] = 0.0f;
        gemm3acc(D, aH0H, aH0L, bW1IH, bW1IL, akl, axm, bkl, bxm);
        if (t > 0) gemm3acc(D, aH1H, aH1L, bW1HH, bW1HL, akl, axm, bkl, bxm);
        bar_grp(bid);                                      // h1 reads done
        float fcacc = epilogue<1>(D, cs1, odd, jconst, eH1H, eH1L, exm, sBias1, sFcw);

        // fc reduction: combine the two lanes sharing a row, stash per (row, ng)
        fcacc += __shfl_xor_sync(0xffffffffu, fcacc, 2);
        if (tig == 0)      sRed[(grp * 16 + gid) * 4 + ng]     = fcacc;
        else if (tig == 1) sRed[(grp * 16 + gid + 8) * 4 + ng] = fcacc;
        bar_grp(bid);                                      // h1(t) + sRed visible
        const int gtid = tid & 127;
        if (gtid < 16) {
            const int row = grp * 16 + gtid;
            out[(size_t)(gbase + row) * T + t] =
                sRed[row * 4] + sRed[row * 4 + 1] + sRed[row * 4 + 2] + sRed[row * 4 + 3] + bfc_v;
        }
    }
}

// ===========================================================================
extern "C" void kernel_launch(void* const* d_in, const int* in_sizes, int n_in,
                              void* d_out, int out_size)
{
    const float* z    = (const float*)d_in[0];
    const float* Wih0 = (const float*)d_in[1];
    const float* Whh0 = (const float*)d_in[2];
    const float* bih0 = (const float*)d_in[3];
    const float* bhh0 = (const float*)d_in[4];
    const float* Wih1 = (const float*)d_in[5];
    const float* Whh1 = (const float*)d_in[6];
    const float* bih1 = (const float*)d_in[7];
    const float* bhh1 = (const float*)d_in[8];
    const float* Wfc  = (const float*)d_in[9];
    const float* bfc  = (const float*)d_in[10];
    float* out = (float*)d_out;

    const int B = in_sizes[0] / 16;      // 65536

    cudaFuncSetAttribute(lstm_hmma_kernel,
                         cudaFuncAttributeMaxDynamicSharedMemorySize, SMEM_TOTAL);
    lstm_hmma_kernel<<<B / MR, NT, SMEM_TOTAL>>>(
        z, Wih0, Whh0, bih0, bhh0, Wih1, Whh1, bih1, bhh1, Wfc, bfc, out);
}

// round 10
// speedup vs baseline: 7.5137x; 1.2471x over previous
#include <cuda_runtime.h>
#include <cuda_fp16.h>
#include <cstdint>

#define DI __device__ __forceinline__

constexpr int T  = 15;
constexpr int NT = 512;      // 16 warps: 4 groups x 4 warps
constexpr int MR = 64;       // batch rows per CTA (16 per group)

// ---------------- SMEM byte offsets ----------------
// Weight tiles: [256 n'][64 k] fp16, 128B rows, SW128 xor swizzle (32768 B each)
constexpr int O_W0H  = 0;         // Whh0 (fp16)
constexpr int O_W1I  = 32768;     // Wih1
constexpr int O_W1H  = 65536;     // Whh1
// h-state tiles: [64 rows][64 k] fp16 SW128 (8192 B each), hi + lo split
constexpr int O_H0H  = 98304;
constexpr int O_H0L  = 106496;
constexpr int O_H1H  = 114688;
constexpr int O_H1L  = 122880;
constexpr int O_BIAS1 = 131072;   // 64 x float4 (i,f,g,o)
constexpr int O_FCW   = 132096;   // 64 floats
constexpr int O_SRED  = 132352;   // 64 rows x 4 floats
constexpr int SMEM_TOTAL = 133376;

DI uint32_t smem_u32(const void* p) {
    uint32_t a;
    asm("{ .reg .u64 t; cvta.to.shared.u64 t, %1; cvt.u32.u64 %0, t; }" : "=r"(a) : "l"(p));
    return a;
}
DI void sts16(uint32_t addr, unsigned short u) {
    asm volatile("st.shared.b16 [%0], %1;" :: "r"(addr), "h"(u) : "memory");
}
DI void ldsm4(uint32_t* r, uint32_t addr) {
    asm volatile("ldmatrix.sync.aligned.m8n8.x4.shared.b16 {%0,%1,%2,%3}, [%4];"
                 : "=r"(r[0]), "=r"(r[1]), "=r"(r[2]), "=r"(r[3]) : "r"(addr));
}
DI void mma4(float* d, const uint32_t* a, uint32_t b0, uint32_t b1, const float* c) {
    asm("mma.sync.aligned.m16n8k16.row.col.f32.f16.f16.f32 "
        "{%0,%1,%2,%3},{%4,%5,%6,%7},{%8,%9},{%10,%11,%12,%13};"
        : "=f"(d[0]), "=f"(d[1]), "=f"(d[2]), "=f"(d[3])
        : "r"(a[0]), "r"(a[1]), "r"(a[2]), "r"(a[3]), "r"(b0), "r"(b1),
          "f"(c[0]), "f"(c[1]), "f"(c[2]), "f"(c[3]));
}
// named barrier: per-group sync (128 threads), with memory ordering
DI void bar_grp(int id) {
    asm volatile("bar.sync %0, 128;" :: "r"(id) : "memory");
}

// swizzled offset inside a [n'][64k] fp16 tile with 128B rows
DI uint32_t swoff(int np, int k) {
    return (uint32_t)(np * 128 + k * 2) ^ (uint32_t)((np & 7) << 4);
}

// ---- exact activations (EX2 + RCP, rel err ~2^-22) ----
DI float sigf(float x)  { return __fdividef(1.0f, 1.0f + __expf(-x)); }
DI float tanh_(float x) {
    float e = __expf(-2.0f * fabsf(x));
    return copysignf(__fdividef(1.0f - e, 1.0f + e), x);
}

// 2-term split-fp16 GEMM, accumulate into D[32]:
// D += Ahi*Wh + Alo*Wh over K=64; warp n-range = 64 (4 chunks of 16)
DI void gemm2acc(float* D, uint32_t aHi, uint32_t aLo, uint32_t bW,
                 uint32_t akl, uint32_t axm, uint32_t bkl, uint32_t bxm)
{
    #pragma unroll
    for (int ks = 0; ks < 4; ks++) {
        const uint32_t kA = ((uint32_t)(ks * 32) + akl) ^ axm;
        const uint32_t kB = ((uint32_t)(ks * 32) + bkl) ^ bxm;
        uint32_t ah[4], al[4];
        ldsm4(ah, aHi + kA);
        ldsm4(al, aLo + kA);
        #pragma unroll
        for (int p = 0; p < 4; p++) {
            uint32_t bh[4];
            ldsm4(bh, bW + p * 2048 + kB);
            float* d0 = D + p * 8;
            mma4(d0,     ah, bh[0], bh[1], d0);
            mma4(d0 + 4, ah, bh[2], bh[3], d0 + 4);
            mma4(d0,     al, bh[0], bh[1], d0);
            mma4(d0 + 4, al, bh[2], bh[3], d0 + 4);
        }
    }
}

// epilogue: gate exchange, LSTM cell update, h split writeback. LAYER 1 adds
// bias (layer-0 bias folded into zp) and accumulates the fc dot product.
template<int LAYER>
DI float epilogue(float* D, float* cs, int odd, int jconst,
                  uint32_t eHi, uint32_t eLo, uint32_t exm,
                  const float4* sBias1, const float* sFcw)
{
    float fcacc = 0.0f;
    #pragma unroll
    for (int p = 0; p < 4; p++) {
        #pragma unroll
        for (int q = 0; q < 2; q++) {
            const int di = p * 8 + q * 4;
            float x0 = D[di], x1 = D[di + 1], x2 = D[di + 2], x3 = D[di + 3];
            float e1 = __shfl_xor_sync(0xffffffffu, odd ? x0 : x2, 1);
            float e2 = __shfl_xor_sync(0xffffffffu, odd ? x1 : x3, 1);
            float gi = odd ? e1 : x0;
            float gf = odd ? e2 : x1;
            float gg = odd ? x2 : e1;
            float go = odd ? x3 : e2;
            const int j = jconst + p * 4 + q * 2;
            if (LAYER == 1) {
                const float4 b = sBias1[j];
                gi += b.x; gf += b.y; gg += b.z; go += b.w;
            }
            const float i_ = sigf(gi);
            const float f_ = sigf(gf);
            const float g_ = tanh_(gg);
            const float o_ = sigf(go);
            const int ci = p * 2 + q;
            const float cn = fmaf(f_, cs[ci], i_ * g_);
            cs[ci] = cn;
            const float h = o_ * tanh_(cn);
            if (LAYER == 1) fcacc = fmaf(h, sFcw[j], fcacc);
            const __half hh = __float2half_rn(h);
            const float lo = h - __half2float(hh);
            const uint32_t co = ((uint32_t)(j * 2)) ^ exm;
            sts16(eHi + co, __half_as_ushort(hh));
            sts16(eLo + co, __half_as_ushort(__float2half_rn(lo)));
        }
    }
    return fcacc;
}

// ===========================================================================
__global__ void __launch_bounds__(NT, 1) lstm_hmma_kernel(
    const float* __restrict__ z,
    const float* __restrict__ Wih0, const float* __restrict__ Whh0,
    const float* __restrict__ bih0, const float* __restrict__ bhh0,
    const float* __restrict__ Wih1, const float* __restrict__ Whh1,
    const float* __restrict__ bih1, const float* __restrict__ bhh1,
    const float* __restrict__ Wfc,  const float* __restrict__ bfc,
    float* __restrict__ out)
{
    extern __shared__ char sm[];
    const uint32_t smb = smem_u32(sm);
    const int tid  = threadIdx.x;
    const int lane = tid & 31;
    const int w    = tid >> 5;
    const int grp  = w >> 2;       // row group: rows grp*16 .. +15
    const int ng   = w & 3;        // n-quarter: n' in [ng*64, ng*64+64)
    const int bid  = grp + 1;      // named barrier id

    // ---- ldmatrix lane addressing constants ----
    const int j8  = lane & 7;
    const int sel = lane >> 3;
    const int arow = grp * 16 + j8 + (sel & 1) * 8;     // local A row this lane feeds
    const uint32_t axm = (uint32_t)j8 << 4;             // arow & 7 == j8
    const uint32_t akl = (uint32_t)(sel >> 1) << 4;
    const int bnl = (sel >> 1) * 8 + j8;                // B row within 16-row chunk
    const uint32_t bxm = (uint32_t)j8 << 4;
    const uint32_t bkl = (uint32_t)(sel & 1) << 4;

    const uint32_t aOff = (uint32_t)arow * 128;
    const uint32_t bOff = (uint32_t)(ng * 64 + bnl) * 128;
    const uint32_t aH0H = smb + O_H0H + aOff, aH0L = smb + O_H0L + aOff;
    const uint32_t aH1H = smb + O_H1H + aOff, aH1L = smb + O_H1L + aOff;
    const uint32_t bW0  = smb + O_W0H + bOff;
    const uint32_t bW1I = smb + O_W1I + bOff;
    const uint32_t bW1H = smb + O_W1H + bOff;

    // ---- epilogue lane constants ----
    const int gid = lane >> 2, tig = lane & 3;
    const int odd = tig & 1;
    const int erow = grp * 16 + gid + 8 * odd;          // local row this lane updates
    const uint32_t eOff = (uint32_t)erow * 128;
    const uint32_t exm  = (uint32_t)(erow & 7) << 4;
    const uint32_t eH0H = smb + O_H0H + eOff, eH0L = smb + O_H0L + eOff;
    const uint32_t eH1H = smb + O_H1H + eOff, eH1L = smb + O_H1L + eOff;
    const int jconst = ng * 16 + (tig >> 1);

    float4* sBias1 = (float4*)(sm + O_BIAS1);
    float*  sFcw   = (float*)(sm + O_FCW);
    float*  sRed   = (float*)(sm + O_SRED);

    // ======== init: repack weights (fp16, gate-interleaved n'=4j+g) ========
    for (int idx = tid; idx < 16384; idx += NT) {
        const int r = idx >> 6, k = idx & 63;
        const int g = r >> 6, j = r & 63;
        const uint32_t off = swoff(j * 4 + g, k);
        *(__half*)(sm + O_W0H + off) = __float2half_rn(Whh0[idx]);
        *(__half*)(sm + O_W1I + off) = __float2half_rn(Wih1[idx]);
        *(__half*)(sm + O_W1H + off) = __float2half_rn(Whh1[idx]);
    }
    // stage Wih0 (fp32) into the h-tile area (16KB) + bias0 sums (1KB)
    float* sWz = (float*)(sm + O_H0H);     // [256][16] fp32 (spans H0H+H0L)
    float* sB0 = (float*)(sm + O_H1H);     // [256]
    for (int idx = tid; idx < 4096; idx += NT) sWz[idx] = Wih0[idx];
    for (int idx = tid; idx < 256;  idx += NT) sB0[idx] = bih0[idx] + bhh0[idx];
    if (tid < 64) {
        sBias1[tid] = make_float4(bih1[tid] + bhh1[tid],
                                  bih1[64 + tid] + bhh1[64 + tid],
                                  bih1[128 + tid] + bhh1[128 + tid],
                                  bih1[192 + tid] + bhh1[192 + tid]);
        sFcw[tid] = Wfc[tid];
    }
    const float bfc_v = __ldg(bfc);
    __syncthreads();

    // ======== one-time exact z-projection + bias0 into zp (D-fragment layout) ====
    const int gbase = blockIdx.x * MR;
    float zp[32];
    {
        float zr0[16], zr1[16];
        const int r0 = gbase + grp * 16 + gid;
        #pragma unroll
        for (int k = 0; k < 16; k++) {
            zr0[k] = z[(size_t)r0 * 16 + k];
            zr1[k] = z[(size_t)(r0 + 8) * 16 + k];
        }
        #pragma unroll
        for (int p = 0; p < 4; p++) {
            #pragma unroll
            for (int q = 0; q < 2; q++) {
                #pragma unroll
                for (int e = 0; e < 2; e++) {
                    const int np = ng * 64 + p * 16 + q * 8 + tig * 2 + e;
                    const int orig = (np & 3) * 64 + (np >> 2);
                    const float* wr = sWz + orig * 16;
                    float s0 = sB0[orig], s1 = s0;
                    #pragma unroll
                    for (int k = 0; k < 16; k++) {
                        const float wv = wr[k];
                        s0 = fmaf(zr0[k], wv, s0);
                        s1 = fmaf(zr1[k], wv, s1);
                    }
                    zp[p * 8 + q * 4 + e]     = s0;
                    zp[p * 8 + q * 4 + 2 + e] = s1;
                }
            }
        }
    }
    __syncthreads();   // staging reads done before h tiles get overwritten

    // ======== recurrence (each 16-row group runs independently) ========
    float cs0[8], cs1[8];
    #pragma unroll
    for (int i = 0; i < 8; i++) { cs0[i] = 0.0f; cs1[i] = 0.0f; }

    #pragma unroll 1
    for (int t = 0; t < T; t++) {
        float D[32];

        // ----- layer 0: D = zp (+ h0(t-1)·Whh0, 2-term) -----
        #pragma unroll
        for (int i = 0; i < 32; i++) D[i] = zp[i];
        if (t > 0) gemm2acc(D, aH0H, aH0L, bW0, akl, axm, bkl, bxm);
        bar_grp(bid);                                      // h0 reads done
        epilogue<0>(D, cs0, odd, jconst, eH0H, eH0L, exm, sBias1, sFcw);
        bar_grp(bid);                                      // h0(t) visible

        // ----- layer 1: D = h0(t)·Wih1 (+ h1(t-1)·Whh1) -----
        #pragma unroll
        for (int i = 0; i < 32; i++) D[i] = 0.0f;
        gemm2acc(D, aH0H, aH0L, bW1I, akl, axm, bkl, bxm);
        if (t > 0) gemm2acc(D, aH1H, aH1L, bW1H, akl, axm, bkl, bxm);
        bar_grp(bid);                                      // h1 reads done
        float fcacc = epilogue<1>(D, cs1, odd, jconst, eH1H, eH1L, exm, sBias1, sFcw);

        // fc reduction: combine the two lanes sharing a row, stash per (row, ng)
        fcacc += __shfl_xor_sync(0xffffffffu, fcacc, 2);
        if (tig == 0)      sRed[(grp * 16 + gid) * 4 + ng]     = fcacc;
        else if (tig == 1) sRed[(grp * 16 + gid + 8) * 4 + ng] = fcacc;
        bar_grp(bid);                                      // h1(t) + sRed visible
        const int gtid = tid & 127;
        if (gtid < 16) {
            const int row = grp * 16 + gtid;
            out[(size_t)(gbase + row) * T + t] =
                sRed[row * 4] + sRed[row * 4 + 1] + sRed[row * 4 + 2] + sRed[row * 4 + 3] + bfc_v;
        }
    }
}

// ===========================================================================
extern "C" void kernel_launch(void* const* d_in, const int* in_sizes, int n_in,
                              void* d_out, int out_size)
{
    const float* z    = (const float*)d_in[0];
    const float* Wih0 = (const float*)d_in[1];
    const float* Whh0 = (const float*)d_in[2];
    const float* bih0 = (const float*)d_in[3];
    const float* bhh0 = (const float*)d_in[4];
    const float* Wih1 = (const float*)d_in[5];
    const float* Whh1 = (const float*)d_in[6];
    const float* bih1 = (const float*)d_in[7];
    const float* bhh1 = (const float*)d_in[8];
    const float* Wfc  = (const float*)d_in[9];
    const float* bfc  = (const float*)d_in[10];
    float* out = (float*)d_out;

    const int B = in_sizes[0] / 16;      // 65536

    cudaFuncSetAttribute(lstm_hmma_kernel,
                         cudaFuncAttributeMaxDynamicSharedMemorySize, SMEM_TOTAL);
    lstm_hmma_kernel<<<B / MR, NT, SMEM_TOTAL>>>(
        z, Wih0, Whh0, bih0, bhh0, Wih1, Whh1, bih1, bhh1, Wfc, bfc, out);
}

// round 11
// speedup vs baseline: 9.1180x; 1.2135x over previous
#include <cuda_runtime.h>
#include <cuda_fp16.h>
#include <cstdint>

#define DI __device__ __forceinline__

constexpr int T  = 15;
constexpr int NT = 512;      // 16 warps: 4 groups x 4 warps
constexpr int MR = 64;       // batch rows per CTA (16 per group)

// ---------------- SMEM byte offsets ----------------
// Weight tiles: [256 n'][64 k] fp16, 128B rows, SW128 xor swizzle (32768 B each)
constexpr int O_W0   = 0;         // Whh0 (fp16)
constexpr int O_W1I  = 32768;     // Wih1
constexpr int O_W1H  = 65536;     // Whh1
// h-state tiles: [64 rows][64 k] fp16 SW128 (8192 B each), single fp16
constexpr int O_H0   = 98304;
constexpr int O_H1   = 106496;
constexpr int O_BIAS1 = 114688;   // 64 x float4 (i,f,g,o)
constexpr int O_FCW   = 115712;   // 64 floats
constexpr int O_SRED  = 115968;   // 64 rows x 4 floats
constexpr int SMEM_TOTAL = 116992;

DI uint32_t smem_u32(const void* p) {
    uint32_t a;
    asm("{ .reg .u64 t; cvta.to.shared.u64 t, %1; cvt.u32.u64 %0, t; }" : "=r"(a) : "l"(p));
    return a;
}
DI void sts16(uint32_t addr, unsigned short u) {
    asm volatile("st.shared.b16 [%0], %1;" :: "r"(addr), "h"(u) : "memory");
}
DI void ldsm4(uint32_t* r, uint32_t addr) {
    asm volatile("ldmatrix.sync.aligned.m8n8.x4.shared.b16 {%0,%1,%2,%3}, [%4];"
                 : "=r"(r[0]), "=r"(r[1]), "=r"(r[2]), "=r"(r[3]) : "r"(addr));
}
DI void mma4(float* d, const uint32_t* a, uint32_t b0, uint32_t b1, const float* c) {
    asm("mma.sync.aligned.m16n8k16.row.col.f32.f16.f16.f32 "
        "{%0,%1,%2,%3},{%4,%5,%6,%7},{%8,%9},{%10,%11,%12,%13};"
        : "=f"(d[0]), "=f"(d[1]), "=f"(d[2]), "=f"(d[3])
        : "r"(a[0]), "r"(a[1]), "r"(a[2]), "r"(a[3]), "r"(b0), "r"(b1),
          "f"(c[0]), "f"(c[1]), "f"(c[2]), "f"(c[3]));
}
// named barrier: per-group sync (128 threads), with memory ordering
DI void bar_grp(int id) {
    asm volatile("bar.sync %0, 128;" :: "r"(id) : "memory");
}

// swizzled offset inside a [n'][64k] fp16 tile with 128B rows
DI uint32_t swoff(int np, int k) {
    return (uint32_t)(np * 128 + k * 2) ^ (uint32_t)((np & 7) << 4);
}

// ---- exact activations (EX2 + RCP, rel err ~2^-22) ----
DI float sigf(float x)  { return __fdividef(1.0f, 1.0f + __expf(-x)); }
DI float tanh_(float x) {
    float e = __expf(-2.0f * fabsf(x));
    return copysignf(__fdividef(1.0f - e, 1.0f + e), x);
}

// 1-term fp16 GEMM, accumulate into D[32]:
// D += A*W over K=64; warp n-range = 64 (4 chunks of 16)
DI void gemm1acc(float* D, uint32_t aH, uint32_t bW,
                 uint32_t akl, uint32_t axm, uint32_t bkl, uint32_t bxm)
{
    #pragma unroll
    for (int ks = 0; ks < 4; ks++) {
        const uint32_t kA = ((uint32_t)(ks * 32) + akl) ^ axm;
        const uint32_t kB = ((uint32_t)(ks * 32) + bkl) ^ bxm;
        uint32_t ah[4];
        ldsm4(ah, aH + kA);
        #pragma unroll
        for (int p = 0; p < 4; p++) {
            uint32_t bh[4];
            ldsm4(bh, bW + p * 2048 + kB);
            float* d0 = D + p * 8;
            mma4(d0,     ah, bh[0], bh[1], d0);
            mma4(d0 + 4, ah, bh[2], bh[3], d0 + 4);
        }
    }
}

// epilogue: gate exchange, LSTM cell update, h writeback (fp16). LAYER 1 adds
// bias (layer-0 bias folded into zp) and accumulates the fc dot product.
template<int LAYER>
DI float epilogue(float* D, float* cs, int odd, int jconst,
                  uint32_t eH, uint32_t exm,
                  const float4* sBias1, const float* sFcw)
{
    float fcacc = 0.0f;
    #pragma unroll
    for (int p = 0; p < 4; p++) {
        #pragma unroll
        for (int q = 0; q < 2; q++) {
            const int di = p * 8 + q * 4;
            float x0 = D[di], x1 = D[di + 1], x2 = D[di + 2], x3 = D[di + 3];
            float e1 = __shfl_xor_sync(0xffffffffu, odd ? x0 : x2, 1);
            float e2 = __shfl_xor_sync(0xffffffffu, odd ? x1 : x3, 1);
            float gi = odd ? e1 : x0;
            float gf = odd ? e2 : x1;
            float gg = odd ? x2 : e1;
            float go = odd ? x3 : e2;
            const int j = jconst + p * 4 + q * 2;
            if (LAYER == 1) {
                const float4 b = sBias1[j];
                gi += b.x; gf += b.y; gg += b.z; go += b.w;
            }
            const float i_ = sigf(gi);
            const float f_ = sigf(gf);
            const float g_ = tanh_(gg);
            const float o_ = sigf(go);
            const int ci = p * 2 + q;
            const float cn = fmaf(f_, cs[ci], i_ * g_);
            cs[ci] = cn;
            const float h = o_ * tanh_(cn);
            if (LAYER == 1) fcacc = fmaf(h, sFcw[j], fcacc);
            const uint32_t co = ((uint32_t)(j * 2)) ^ exm;
            sts16(eH + co, __half_as_ushort(__float2half_rn(h)));
        }
    }
    return fcacc;
}

// ===========================================================================
__global__ void __launch_bounds__(NT, 1) lstm_hmma_kernel(
    const float* __restrict__ z,
    const float* __restrict__ Wih0, const float* __restrict__ Whh0,
    const float* __restrict__ bih0, const float* __restrict__ bhh0,
    const float* __restrict__ Wih1, const float* __restrict__ Whh1,
    const float* __restrict__ bih1, const float* __restrict__ bhh1,
    const float* __restrict__ Wfc,  const float* __restrict__ bfc,
    float* __restrict__ out)
{
    extern __shared__ char sm[];
    const uint32_t smb = smem_u32(sm);
    const int tid  = threadIdx.x;
    const int lane = tid & 31;
    const int w    = tid >> 5;
    const int grp  = w >> 2;       // row group: rows grp*16 .. +15
    const int ng   = w & 3;        // n-quarter: n' in [ng*64, ng*64+64)
    const int bid  = grp + 1;      // named barrier id

    // ---- ldmatrix lane addressing constants ----
    const int j8  = lane & 7;
    const int sel = lane >> 3;
    const int arow = grp * 16 + j8 + (sel & 1) * 8;     // local A row this lane feeds
    const uint32_t axm = (uint32_t)j8 << 4;             // arow & 7 == j8
    const uint32_t akl = (uint32_t)(sel >> 1) << 4;
    const int bnl = (sel >> 1) * 8 + j8;                // B row within 16-row chunk
    const uint32_t bxm = (uint32_t)j8 << 4;
    const uint32_t bkl = (uint32_t)(sel & 1) << 4;

    const uint32_t aOff = (uint32_t)arow * 128;
    const uint32_t bOff = (uint32_t)(ng * 64 + bnl) * 128;
    const uint32_t aH0 = smb + O_H0 + aOff;
    const uint32_t aH1 = smb + O_H1 + aOff;
    const uint32_t bW0  = smb + O_W0 + bOff;
    const uint32_t bW1I = smb + O_W1I + bOff;
    const uint32_t bW1H = smb + O_W1H + bOff;

    // ---- epilogue lane constants ----
    const int gid = lane >> 2, tig = lane & 3;
    const int odd = tig & 1;
    const int erow = grp * 16 + gid + 8 * odd;          // local row this lane updates
    const uint32_t eOff = (uint32_t)erow * 128;
    const uint32_t exm  = (uint32_t)(erow & 7) << 4;
    const uint32_t eH0 = smb + O_H0 + eOff;
    const uint32_t eH1 = smb + O_H1 + eOff;
    const int jconst = ng * 16 + (tig >> 1);

    float4* sBias1 = (float4*)(sm + O_BIAS1);
    float*  sFcw   = (float*)(sm + O_FCW);
    float*  sRed   = (float*)(sm + O_SRED);

    // ======== init: repack weights (fp16, gate-interleaved n'=4j+g) ========
    for (int idx = tid; idx < 16384; idx += NT) {
        const int r = idx >> 6, k = idx & 63;
        const int g = r >> 6, j = r & 63;
        const uint32_t off = swoff(j * 4 + g, k);
        *(__half*)(sm + O_W0  + off) = __float2half_rn(Whh0[idx]);
        *(__half*)(sm + O_W1I + off) = __float2half_rn(Wih1[idx]);
        *(__half*)(sm + O_W1H + off) = __float2half_rn(Whh1[idx]);
    }
    // stage Wih0 (fp32) in the h-tile area (16KB) + bias0 sums in SRED (1KB)
    float* sWz = (float*)(sm + O_H0);      // [256][16] fp32 (spans H0+H1)
    float* sB0 = (float*)(sm + O_SRED);    // [256]
    for (int idx = tid; idx < 4096; idx += NT) sWz[idx] = Wih0[idx];
    for (int idx = tid; idx < 256;  idx += NT) sB0[idx] = bih0[idx] + bhh0[idx];
    if (tid < 64) {
        sBias1[tid] = make_float4(bih1[tid] + bhh1[tid],
                                  bih1[64 + tid] + bhh1[64 + tid],
                                  bih1[128 + tid] + bhh1[128 + tid],
                                  bih1[192 + tid] + bhh1[192 + tid]);
        sFcw[tid] = Wfc[tid];
    }
    const float bfc_v = __ldg(bfc);
    __syncthreads();

    // ======== one-time exact z-projection + bias0 into zp (D-fragment layout) ====
    const int gbase = blockIdx.x * MR;
    float zp[32];
    {
        float zr0[16], zr1[16];
        const int r0 = gbase + grp * 16 + gid;
        #pragma unroll
        for (int k = 0; k < 16; k++) {
            zr0[k] = z[(size_t)r0 * 16 + k];
            zr1[k] = z[(size_t)(r0 + 8) * 16 + k];
        }
        #pragma unroll
        for (int p = 0; p < 4; p++) {
            #pragma unroll
            for (int q = 0; q < 2; q++) {
                #pragma unroll
                for (int e = 0; e < 2; e++) {
                    const int np = ng * 64 + p * 16 + q * 8 + tig * 2 + e;
                    const int orig = (np & 3) * 64 + (np >> 2);
                    const float* wr = sWz + orig * 16;
                    float s0 = sB0[orig], s1 = s0;
                    #pragma unroll
                    for (int k = 0; k < 16; k++) {
                        const float wv = wr[k];
                        s0 = fmaf(zr0[k], wv, s0);
                        s1 = fmaf(zr1[k], wv, s1);
                    }
                    zp[p * 8 + q * 4 + e]     = s0;
                    zp[p * 8 + q * 4 + 2 + e] = s1;
                }
            }
        }
    }
    __syncthreads();   // staging reads done before h tiles get overwritten

    // ======== recurrence (each 16-row group runs independently) ========
    float cs0[8], cs1[8];
    #pragma unroll
    for (int i = 0; i < 8; i++) { cs0[i] = 0.0f; cs1[i] = 0.0f; }

    #pragma unroll 1
    for (int t = 0; t < T; t++) {
        float D[32];

        // ----- layer 0: D = zp (+ h0(t-1)·Whh0) -----
        #pragma unroll
        for (int i = 0; i < 32; i++) D[i] = zp[i];
        if (t > 0) gemm1acc(D, aH0, bW0, akl, axm, bkl, bxm);
        bar_grp(bid);                                      // h0 reads done
        epilogue<0>(D, cs0, odd, jconst, eH0, exm, sBias1, sFcw);
        bar_grp(bid);                                      // h0(t) visible

        // ----- layer 1: D = h0(t)·Wih1 (+ h1(t-1)·Whh1) -----
        #pragma unroll
        for (int i = 0; i < 32; i++) D[i] = 0.0f;
        gemm1acc(D, aH0, bW1I, akl, axm, bkl, bxm);
        if (t > 0) gemm1acc(D, aH1, bW1H, akl, axm, bkl, bxm);
        bar_grp(bid);                                      // h1 reads done
        float fcacc = epilogue<1>(D, cs1, odd, jconst, eH1, exm, sBias1, sFcw);

        // fc reduction: combine the two lanes sharing a row, stash per (row, ng)
        fcacc += __shfl_xor_sync(0xffffffffu, fcacc, 2);
        if (tig == 0)      sRed[(grp * 16 + gid) * 4 + ng]     = fcacc;
        else if (tig == 1) sRed[(grp * 16 + gid + 8) * 4 + ng] = fcacc;
        bar_grp(bid);                                      // h1(t) + sRed visible
        const int gtid = tid & 127;
        if (gtid < 16) {
            const int row = grp * 16 + gtid;
            out[(size_t)(gbase + row) * T + t] =
                sRed[row * 4] + sRed[row * 4 + 1] + sRed[row * 4 + 2] + sRed[row * 4 + 3] + bfc_v;
        }
    }
}

// ===========================================================================
extern "C" void kernel_launch(void* const* d_in, const int* in_sizes, int n_in,
                              void* d_out, int out_size)
{
    const float* z    = (const float*)d_in[0];
    const float* Wih0 = (const float*)d_in[1];
    const float* Whh0 = (const float*)d_in[2];
    const float* bih0 = (const float*)d_in[3];
    const float* bhh0 = (const float*)d_in[4];
    const float* Wih1 = (const float*)d_in[5];
    const float* Whh1 = (const float*)d_in[6];
    const float* bih1 = (const float*)d_in[7];
    const float* bhh1 = (const float*)d_in[8];
    const float* Wfc  = (const float*)d_in[9];
    const float* bfc  = (const float*)d_in[10];
    float* out = (float*)d_out;

    const int B = in_sizes[0] / 16;      // 65536

    cudaFuncSetAttribute(lstm_hmma_kernel,
                         cudaFuncAttributeMaxDynamicSharedMemorySize, SMEM_TOTAL);
    lstm_hmma_kernel<<<B / MR, NT, SMEM_TOTAL>>>(
        z, Wih0, Whh0, bih0, bhh0, Wih1, Whh1, bih1, bhh1, Wfc, bfc, out);
}

// round 12
// speedup vs baseline: 11.2635x; 1.2353x over previous
#include <cuda_runtime.h>
#include <cuda_fp16.h>
#include <cstdint>

#define DI __device__ __forceinline__

constexpr int T  = 15;
constexpr int NT = 512;      // 16 warps: 4 groups x 4 warps
constexpr int MR = 64;       // batch rows per CTA (16 per group)

// ---------------- SMEM byte offsets ----------------
// Weight tiles: [256 n'][64 k] fp16, 128B rows, SW128 xor swizzle (32768 B each)
constexpr int O_W0   = 0;         // Whh0 (fp16)
constexpr int O_W1I  = 32768;     // Wih1
constexpr int O_W1H  = 65536;     // Whh1
// h-state tiles: [64 rows][64 k] fp16 SW128 (8192 B each)
constexpr int O_H0   = 98304;
constexpr int O_H1   = 106496;
constexpr int O_BIAS1 = 114688;   // 64 x float4 (i,f,g,o)
constexpr int O_FCW   = 115712;   // 64 floats
constexpr int O_SRED  = 115968;   // 64 rows x 4 floats
constexpr int SMEM_TOTAL = 116992;

DI uint32_t smem_u32(const void* p) {
    uint32_t a;
    asm("{ .reg .u64 t; cvta.to.shared.u64 t, %1; cvt.u32.u64 %0, t; }" : "=r"(a) : "l"(p));
    return a;
}
DI void sts16(uint32_t addr, unsigned short u) {
    asm volatile("st.shared.b16 [%0], %1;" :: "r"(addr), "h"(u) : "memory");
}
DI void ldsm4(uint32_t* r, uint32_t addr) {
    asm volatile("ldmatrix.sync.aligned.m8n8.x4.shared.b16 {%0,%1,%2,%3}, [%4];"
                 : "=r"(r[0]), "=r"(r[1]), "=r"(r[2]), "=r"(r[3]) : "r"(addr));
}
DI void mma4(float* d, const uint32_t* a, uint32_t b0, uint32_t b1, const float* c) {
    asm("mma.sync.aligned.m16n8k16.row.col.f32.f16.f16.f32 "
        "{%0,%1,%2,%3},{%4,%5,%6,%7},{%8,%9},{%10,%11,%12,%13};"
        : "=f"(d[0]), "=f"(d[1]), "=f"(d[2]), "=f"(d[3])
        : "r"(a[0]), "r"(a[1]), "r"(a[2]), "r"(a[3]), "r"(b0), "r"(b1),
          "f"(c[0]), "f"(c[1]), "f"(c[2]), "f"(c[3]));
}
// named barrier: per-group sync (128 threads), with memory ordering
DI void bar_grp(int id) {
    asm volatile("bar.sync %0, 128;" :: "r"(id) : "memory");
}

// swizzled offset inside a [n'][64k] fp16 tile with 128B rows
DI uint32_t swoff(int np, int k) {
    return (uint32_t)(np * 128 + k * 2) ^ (uint32_t)((np & 7) << 4);
}

// ---- fast activations: single MUFU.TANH each ----
DI float tanh_(float x) {
    float r;
    asm("tanh.approx.f32 %0, %1;" : "=f"(r) : "f"(x));
    return r;
}
DI float sigf(float x) {                 // 0.5*tanh(x/2) + 0.5
    return fmaf(tanh_(0.5f * x), 0.5f, 0.5f);
}

// 1-term fp16 GEMM, accumulate into D[32]:
// D += A*W over K=64; warp n-range = 64 (4 chunks of 16)
DI void gemm1acc(float* D, uint32_t aH, uint32_t bW,
                 uint32_t akl, uint32_t axm, uint32_t bkl, uint32_t bxm)
{
    #pragma unroll
    for (int ks = 0; ks < 4; ks++) {
        const uint32_t kA = ((uint32_t)(ks * 32) + akl) ^ axm;
        const uint32_t kB = ((uint32_t)(ks * 32) + bkl) ^ bxm;
        uint32_t ah[4];
        ldsm4(ah, aH + kA);
        #pragma unroll
        for (int p = 0; p < 4; p++) {
            uint32_t bh[4];
            ldsm4(bh, bW + p * 2048 + kB);
            float* d0 = D + p * 8;
            mma4(d0,     ah, bh[0], bh[1], d0);
            mma4(d0 + 4, ah, bh[2], bh[3], d0 + 4);
        }
    }
}

// epilogue: gate exchange, LSTM cell update, h writeback (fp16). LAYER 1 adds
// bias (layer-0 bias folded into zp) and accumulates the fc dot product.
template<int LAYER>
DI float epilogue(float* D, float* cs, int odd, int jconst,
                  uint32_t eH, uint32_t exm,
                  const float4* sBias1, const float* sFcw)
{
    float fcacc = 0.0f;
    #pragma unroll
    for (int p = 0; p < 4; p++) {
        #pragma unroll
        for (int q = 0; q < 2; q++) {
            const int di = p * 8 + q * 4;
            float x0 = D[di], x1 = D[di + 1], x2 = D[di + 2], x3 = D[di + 3];
            float e1 = __shfl_xor_sync(0xffffffffu, odd ? x0 : x2, 1);
            float e2 = __shfl_xor_sync(0xffffffffu, odd ? x1 : x3, 1);
            float gi = odd ? e1 : x0;
            float gf = odd ? e2 : x1;
            float gg = odd ? x2 : e1;
            float go = odd ? x3 : e2;
            const int j = jconst + p * 4 + q * 2;
            if (LAYER == 1) {
                const float4 b = sBias1[j];
                gi += b.x; gf += b.y; gg += b.z; go += b.w;
            }
            const float i_ = sigf(gi);
            const float f_ = sigf(gf);
            const float g_ = tanh_(gg);
            const float o_ = sigf(go);
            const int ci = p * 2 + q;
            const float cn = fmaf(f_, cs[ci], i_ * g_);
            cs[ci] = cn;
            const float h = o_ * tanh_(cn);
            if (LAYER == 1) fcacc = fmaf(h, sFcw[j], fcacc);
            const uint32_t co = ((uint32_t)(j * 2)) ^ exm;
            sts16(eH + co, __half_as_ushort(__float2half_rn(h)));
        }
    }
    return fcacc;
}

// ===========================================================================
__global__ void __launch_bounds__(NT, 1) lstm_hmma_kernel(
    const float* __restrict__ z,
    const float* __restrict__ Wih0, const float* __restrict__ Whh0,
    const float* __restrict__ bih0, const float* __restrict__ bhh0,
    const float* __restrict__ Wih1, const float* __restrict__ Whh1,
    const float* __restrict__ bih1, const float* __restrict__ bhh1,
    const float* __restrict__ Wfc,  const float* __restrict__ bfc,
    float* __restrict__ out)
{
    extern __shared__ char sm[];
    const uint32_t smb = smem_u32(sm);
    const int tid  = threadIdx.x;
    const int lane = tid & 31;
    const int w    = tid >> 5;
    const int grp  = w >> 2;       // row group: rows grp*16 .. +15
    const int ng   = w & 3;        // n-quarter: n' in [ng*64, ng*64+64)
    const int bid  = grp + 1;      // named barrier id

    // ---- ldmatrix lane addressing constants ----
    const int j8  = lane & 7;
    const int sel = lane >> 3;
    const int arow = grp * 16 + j8 + (sel & 1) * 8;     // local A row this lane feeds
    const uint32_t axm = (uint32_t)j8 << 4;             // arow & 7 == j8
    const uint32_t akl = (uint32_t)(sel >> 1) << 4;
    const int bnl = (sel >> 1) * 8 + j8;                // B row within 16-row chunk
    const uint32_t bxm = (uint32_t)j8 << 4;
    const uint32_t bkl = (uint32_t)(sel & 1) << 4;

    const uint32_t aOff = (uint32_t)arow * 128;
    const uint32_t bOff = (uint32_t)(ng * 64 + bnl) * 128;
    const uint32_t aH0 = smb + O_H0 + aOff;
    const uint32_t aH1 = smb + O_H1 + aOff;
    const uint32_t bW0  = smb + O_W0 + bOff;
    const uint32_t bW1I = smb + O_W1I + bOff;
    const uint32_t bW1H = smb + O_W1H + bOff;

    // ---- epilogue lane constants ----
    const int gid = lane >> 2, tig = lane & 3;
    const int odd = tig & 1;
    const int erow = grp * 16 + gid + 8 * odd;          // local row this lane updates
    const uint32_t eOff = (uint32_t)erow * 128;
    const uint32_t exm  = (uint32_t)(erow & 7) << 4;
    const uint32_t eH0 = smb + O_H0 + eOff;
    const uint32_t eH1 = smb + O_H1 + eOff;
    const int jconst = ng * 16 + (tig >> 1);

    float4* sBias1 = (float4*)(sm + O_BIAS1);
    float*  sFcw   = (float*)(sm + O_FCW);
    float*  sRed   = (float*)(sm + O_SRED);

    // ======== init: repack weights (fp16, gate-interleaved n'=4j+g) ========
    for (int idx = tid; idx < 16384; idx += NT) {
        const int r = idx >> 6, k = idx & 63;
        const int g = r >> 6, j = r & 63;
        const uint32_t off = swoff(j * 4 + g, k);
        *(__half*)(sm + O_W0  + off) = __float2half_rn(Whh0[idx]);
        *(__half*)(sm + O_W1I + off) = __float2half_rn(Wih1[idx]);
        *(__half*)(sm + O_W1H + off) = __float2half_rn(Whh1[idx]);
    }
    // stage Wih0 (fp32) in the h-tile area (16KB) + bias0 sums in SRED (1KB)
    float* sWz = (float*)(sm + O_H0);      // [256][16] fp32 (spans H0+H1)
    float* sB0 = (float*)(sm + O_SRED);    // [256]
    for (int idx = tid; idx < 4096; idx += NT) sWz[idx] = Wih0[idx];
    for (int idx = tid; idx < 256;  idx += NT) sB0[idx] = bih0[idx] + bhh0[idx];
    if (tid < 64) {
        sBias1[tid] = make_float4(bih1[tid] + bhh1[tid],
                                  bih1[64 + tid] + bhh1[64 + tid],
                                  bih1[128 + tid] + bhh1[128 + tid],
                                  bih1[192 + tid] + bhh1[192 + tid]);
        sFcw[tid] = Wfc[tid];
    }
    const float bfc_v = __ldg(bfc);
    __syncthreads();

    // ======== one-time exact z-projection + bias0 into zp (D-fragment layout) ====
    const int gbase = blockIdx.x * MR;
    float zp[32];
    {
        float zr0[16], zr1[16];
        const int r0 = gbase + grp * 16 + gid;
        #pragma unroll
        for (int k = 0; k < 16; k++) {
            zr0[k] = z[(size_t)r0 * 16 + k];
            zr1[k] = z[(size_t)(r0 + 8) * 16 + k];
        }
        #pragma unroll
        for (int p = 0; p < 4; p++) {
            #pragma unroll
            for (int q = 0; q < 2; q++) {
                #pragma unroll
                for (int e = 0; e < 2; e++) {
                    const int np = ng * 64 + p * 16 + q * 8 + tig * 2 + e;
                    const int orig = (np & 3) * 64 + (np >> 2);
                    const float* wr = sWz + orig * 16;
                    float s0 = sB0[orig], s1 = s0;
                    #pragma unroll
                    for (int k = 0; k < 16; k++) {
                        const float wv = wr[k];
                        s0 = fmaf(zr0[k], wv, s0);
                        s1 = fmaf(zr1[k], wv, s1);
                    }
                    zp[p * 8 + q * 4 + e]     = s0;
                    zp[p * 8 + q * 4 + 2 + e] = s1;
                }
            }
        }
    }
    __syncthreads();   // staging reads done before h tiles get overwritten

    // ======== recurrence (each 16-row group runs independently) ========
    float cs0[8], cs1[8];
    #pragma unroll
    for (int i = 0; i < 8; i++) { cs0[i] = 0.0f; cs1[i] = 0.0f; }

    #pragma unroll 1
    for (int t = 0; t < T; t++) {
        float D[32];

        // ----- layer 0: D = zp (+ h0(t-1)·Whh0) -----
        #pragma unroll
        for (int i = 0; i < 32; i++) D[i] = zp[i];
        if (t > 0) gemm1acc(D, aH0, bW0, akl, axm, bkl, bxm);
        bar_grp(bid);                                      // h0 reads done
        epilogue<0>(D, cs0, odd, jconst, eH0, exm, sBias1, sFcw);
        bar_grp(bid);                                      // h0(t) visible

        // ----- layer 1: D = h0(t)·Wih1 (+ h1(t-1)·Whh1) -----
        #pragma unroll
        for (int i = 0; i < 32; i++) D[i] = 0.0f;
        gemm1acc(D, aH0, bW1I, akl, axm, bkl, bxm);
        if (t > 0) gemm1acc(D, aH1, bW1H, akl, axm, bkl, bxm);
        bar_grp(bid);                                      // h1 reads done
        float fcacc = epilogue<1>(D, cs1, odd, jconst, eH1, exm, sBias1, sFcw);

        // fc reduction: combine the two lanes sharing a row, stash per (row, ng)
        fcacc += __shfl_xor_sync(0xffffffffu, fcacc, 2);
        if (tig == 0)      sRed[(grp * 16 + gid) * 4 + ng]     = fcacc;
        else if (tig == 1) sRed[(grp * 16 + gid + 8) * 4 + ng] = fcacc;
        bar_grp(bid);                                      // h1(t) + sRed visible
        const int gtid = tid & 127;
        if (gtid < 16) {
            const int row = grp * 16 + gtid;
            out[(size_t)(gbase + row) * T + t] =
                sRed[row * 4] + sRed[row * 4 + 1] + sRed[row * 4 + 2] + sRed[row * 4 + 3] + bfc_v;
        }
    }
}

// ===========================================================================
extern "C" void kernel_launch(void* const* d_in, const int* in_sizes, int n_in,
                              void* d_out, int out_size)
{
    const float* z    = (const float*)d_in[0];
    const float* Wih0 = (const float*)d_in[1];
    const float* Whh0 = (const float*)d_in[2];
    const float* bih0 = (const float*)d_in[3];
    const float* bhh0 = (const float*)d_in[4];
    const float* Wih1 = (const float*)d_in[5];
    const float* Whh1 = (const float*)d_in[6];
    const float* bih1 = (const float*)d_in[7];
    const float* bhh1 = (const float*)d_in[8];
    const float* Wfc  = (const float*)d_in[9];
    const float* bfc  = (const float*)d_in[10];
    float* out = (float*)d_out;

    const int B = in_sizes[0] / 16;      // 65536

    cudaFuncSetAttribute(lstm_hmma_kernel,
                         cudaFuncAttributeMaxDynamicSharedMemorySize, SMEM_TOTAL);
    lstm_hmma_kernel<<<B / MR, NT, SMEM_TOTAL>>>(
        z, Wih0, Whh0, bih0, bhh0, Wih1, Whh1, bih1, bhh1, Wfc, bfc, out);
}